// round 16
// baseline (speedup 1.0000x reference)
#include <cuda_runtime.h>
#include <cuda_fp16.h>
#include <cstdint>

#define N_NODES 50000
#define N_EDGES 800000
#define CDIM 128
#define NC (N_NODES * CDIM)
#define E_CAP (N_EDGES + 4 * N_NODES)   // padded edge capacity

typedef unsigned long long u64;

// ---------------- scratch (static device globals; zero-initialized, no allocation) --------
__device__ int      g_cnt[N_NODES];        // always zero at call entry (scan re-zeroes)
__device__ int      g_off[N_NODES + 1];
__device__ int      g_cur[N_NODES];
__device__ float4   g_edge[E_CAP];         // {col-as-bits, vr, vi, 0}; pad slots stay zero
__device__ uint32_t g_yh[NC];              // half2(yr, yi) per (row, channel)

// ---------------- packed f32x2 helpers ----------------
__device__ __forceinline__ u64 pk(float lo, float hi) {
    u64 r; asm("mov.b64 %0, {%1,%2};" : "=l"(r) : "f"(lo), "f"(hi)); return r;
}
__device__ __forceinline__ void upk(u64 v, float& lo, float& hi) {
    asm("mov.b64 {%0,%1}, %2;" : "=f"(lo), "=f"(hi) : "l"(v));
}
__device__ __forceinline__ u64 ffma2(u64 a, u64 b, u64 c) {
    u64 d; asm("fma.rn.f32x2 %0, %1, %2, %3;" : "=l"(d) : "l"(a), "l"(b), "l"(c)); return d;
}
__device__ __forceinline__ uint32_t f2h2(float lo, float hi) {
    __half2 h = __floats2half2_rn(lo, hi);
    return *(uint32_t*)&h;
}
__device__ __forceinline__ u64 h2p(uint32_t h) {   // half2 -> packed f32x2 (u64)
    float2 f = __half22float2(*(__half2*)&h);
    return pk(f.x, f.y);
}

// ---------------- counting sort pipeline (pad-to-4 offsets) ----------------
__global__ void hist_kernel(const int* __restrict__ row) {
    int e = blockIdx.x * blockDim.x + threadIdx.x;
    if (e < N_EDGES) atomicAdd(&g_cnt[row[e]], 1);
}

// single-block coalesced scan: 1024 threads, 49 chunk iterations, shfl block-scan
__global__ __launch_bounds__(1024)
void scan_kernel() {
    __shared__ int wsum[32];
    int t = threadIdx.x, lane = t & 31, wid = t >> 5;
    int run = 0;
    const int ITERS = (N_NODES + 1023) / 1024;  // 49
    for (int it = 0; it < ITERS; it++) {
        int idx = it * 1024 + t;
        int c = (idx < N_NODES) ? g_cnt[idx] : 0;
        int v = (c + 3) & ~3;
        int s = v;
        #pragma unroll
        for (int d = 1; d < 32; d <<= 1) {
            int u = __shfl_up_sync(0xffffffffu, s, d);
            if (lane >= d) s += u;
        }
        if (lane == 31) wsum[wid] = s;
        __syncthreads();
        if (wid == 0) {
            int ws = wsum[lane];
            #pragma unroll
            for (int d = 1; d < 32; d <<= 1) {
                int u = __shfl_up_sync(0xffffffffu, ws, d);
                if (lane >= d) ws += u;
            }
            wsum[lane] = ws;
        }
        __syncthreads();
        int base = (wid > 0) ? wsum[wid - 1] : 0;
        int excl = run + base + s - v;
        if (idx < N_NODES) {
            g_off[idx] = excl;
            g_cur[idx] = excl;
            g_cnt[idx] = 0;          // restore invariant for next call
        }
        run += wsum[31];
        __syncthreads();             // protect wsum before next iteration
    }
    if (t == 0) g_off[N_NODES] = run;
}

__global__ void scatter_kernel(const int* __restrict__ row, const int* __restrict__ col,
                               const float* __restrict__ lr, const float* __restrict__ li) {
    int e = blockIdx.x * blockDim.x + threadIdx.x;
    if (e < N_EDGES) {
        int r = row[e];
        int p = atomicAdd(&g_cur[r], 1);
        g_edge[p] = make_float4(__int_as_float(col[e]), lr[e], li[e], 0.0f);
    }
}

// ---------------- GEMM kernel: Yh = half2(X @ W pairs), complex-pair packed --------------
// R12 structure: W staged once (64KB), A prefetched one tile ahead in registers.
#define GM_TPB    256
#define GM_WPB    8
#define GM_RPW    4
#define GM_ROWS   (GM_WPB * GM_RPW)                      // 32 rows / tile
#define GM_TILES  ((N_NODES + GM_ROWS - 1) / GM_ROWS)    // 1563
#define GM_GRID   (148 * 2)                              // 296 = one full wave @ 2 blk/SM
#define GM_SMEM   (CDIM * CDIM * 4 + GM_ROWS * CDIM * 8) // 64KB W + 32KB A = 98304

#define LOAD_A_REGS(TILE) do {                                                  \
    int rb_ = (TILE) * GM_ROWS + warp * GM_RPW;                                 \
    _Pragma("unroll")                                                           \
    for (int rr = 0; rr < GM_RPW; rr++) {                                       \
        int row_ = min(rb_ + rr, N_NODES - 1);                                  \
        pr[rr][0] = *(const float2*)(Xr + row_ * CDIM + 2 * lane);              \
        pi[rr][0] = *(const float2*)(Xi + row_ * CDIM + 2 * lane);              \
        pr[rr][1] = *(const float2*)(Xr + row_ * CDIM + 64 + 2 * lane);         \
        pi[rr][1] = *(const float2*)(Xi + row_ * CDIM + 64 + 2 * lane);         \
    }                                                                           \
} while (0)

__global__ __launch_bounds__(GM_TPB, 2)
void gemm_kernel(const float* __restrict__ Xr, const float* __restrict__ Xi,
                 const float* __restrict__ W, uint32_t* __restrict__ Yh) {
    extern __shared__ char smraw[];
    float* Wt = (float*)smraw;                        // [128][128], staged once
    u64*   At = (u64*)(smraw + CDIM * CDIM * 4);      // [32 rows][128] (xr,xi) pairs

    int tid  = threadIdx.x;
    int warp = tid >> 5;
    int lane = tid & 31;

    // stage full W once (coalesced float4; 16 per thread)
    {
        const float4* s4 = (const float4*)W;
        float4* d4 = (float4*)Wt;
        #pragma unroll
        for (int i = 0; i < CDIM * CDIM / 4 / GM_TPB; i++)
            d4[i * GM_TPB + tid] = s4[i * GM_TPB + tid];
    }

    // prologue: prefetch first tile's A into registers
    float2 pr[GM_RPW][2], pi[GM_RPW][2];
    LOAD_A_REGS(blockIdx.x);
    __syncthreads();   // W ready

    for (int tile = blockIdx.x; tile < GM_TILES; tile += GM_GRID) {
        int rbase = tile * GM_ROWS + warp * GM_RPW;

        // STS prefetched A (register-sourced, no global latency at this barrier)
        #pragma unroll
        for (int rr = 0; rr < GM_RPW; rr++) {
            #pragma unroll
            for (int seg = 0; seg < 2; seg++) {
                ulonglong2 v;
                v.x = pk(pr[rr][seg].x, pi[rr][seg].x);
                v.y = pk(pr[rr][seg].y, pi[rr][seg].y);
                *(ulonglong2*)&At[(warp * GM_RPW + rr) * CDIM + seg * 64 + 2 * lane] = v;
            }
        }
        __syncthreads();

        // prefetch NEXT tile's A now; latency hides under this tile's compute
        int nt = tile + GM_GRID;
        if (nt < GM_TILES) LOAD_A_REGS(nt);

        u64 acc[GM_RPW][4];
        #pragma unroll
        for (int rr = 0; rr < GM_RPW; rr++)
            #pragma unroll
            for (int c = 0; c < 4; c++) acc[rr][c] = 0ull;

        const u64* Aw = At + warp * GM_RPW * CDIM;
        #pragma unroll 8
        for (int kk = 0; kk < CDIM; kk += 2) {
            float4 w4a = *(const float4*)&Wt[kk * CDIM + 4 * lane];
            float4 w4b = *(const float4*)&Wt[(kk + 1) * CDIM + 4 * lane];
            u64 wa0 = pk(w4a.x, w4a.x), wa1 = pk(w4a.y, w4a.y);
            u64 wa2 = pk(w4a.z, w4a.z), wa3 = pk(w4a.w, w4a.w);
            u64 wb0 = pk(w4b.x, w4b.x), wb1 = pk(w4b.y, w4b.y);
            u64 wb2 = pk(w4b.z, w4b.z), wb3 = pk(w4b.w, w4b.w);
            #pragma unroll
            for (int rr = 0; rr < GM_RPW; rr++) {
                ulonglong2 a = *(const ulonglong2*)&Aw[rr * CDIM + kk];
                acc[rr][0] = ffma2(a.x, wa0, acc[rr][0]);
                acc[rr][1] = ffma2(a.x, wa1, acc[rr][1]);
                acc[rr][2] = ffma2(a.x, wa2, acc[rr][2]);
                acc[rr][3] = ffma2(a.x, wa3, acc[rr][3]);
                acc[rr][0] = ffma2(a.y, wb0, acc[rr][0]);
                acc[rr][1] = ffma2(a.y, wb1, acc[rr][1]);
                acc[rr][2] = ffma2(a.y, wb2, acc[rr][2]);
                acc[rr][3] = ffma2(a.y, wb3, acc[rr][3]);
            }
        }

        // write Y as half2(yr,yi) per channel (one uint4 = lane's 4 channels)
        #pragma unroll
        for (int rr = 0; rr < GM_RPW; rr++) {
            int row = rbase + rr;
            if (row < N_NODES) {
                float lo, hi;
                uint4 o;
                upk(acc[rr][0], lo, hi); o.x = f2h2(lo, hi);
                upk(acc[rr][1], lo, hi); o.y = f2h2(lo, hi);
                upk(acc[rr][2], lo, hi); o.z = f2h2(lo, hi);
                upk(acc[rr][3], lo, hi); o.w = f2h2(lo, hi);
                *(uint4*)&Yh[row * CDIM + 4 * lane] = o;
            }
        }
        __syncthreads();
    }
}

// ---------------- SpMM kernel: out = L_complex @ Y + X  (fp16 gather, cvt-at-load) -------
#define S_TPB 256
#define S_WPB 8
#define S_BLOCKS (148 * 3)   // 444 = one full wave at 3 blocks/SM

// slot state: VR2/VI2 (u64 dup'd edge values) + P0..P3 (converted f32x2 Y pairs).
// compute: 8 clean ffma2; reload: LDS meta -> LDG fp16 -> convert into slot (used 4 later)
#define SB(VR2, VI2, P0, P1, P2, P3, J) do {                                   \
    acV1[0] = ffma2(VR2, P0, acV1[0]); acV2[0] = ffma2(VI2, P0, acV2[0]);      \
    acV1[1] = ffma2(VR2, P1, acV1[1]); acV2[1] = ffma2(VI2, P1, acV2[1]);      \
    acV1[2] = ffma2(VR2, P2, acV1[2]); acV2[2] = ffma2(VI2, P2, acV2[2]);      \
    acV1[3] = ffma2(VR2, P3, acV1[3]); acV2[3] = ffma2(VI2, P3, acV2[3]);      \
    int jn = (J) + 4;                                                          \
    if (jn < cnt) {                                                            \
        float4 md = mrow[jn];                                                  \
        int c = __float_as_int(md.x);                                          \
        uint4 y = *(const uint4*)(YL + (c << 7));                              \
        VR2 = pk(md.y, md.y);                                                  \
        VI2 = pk(md.z, md.z);                                                  \
        P0 = h2p(y.x); P1 = h2p(y.y); P2 = h2p(y.z); P3 = h2p(y.w);            \
    }                                                                          \
} while (0)

#define SLOT_INIT(VR2, VI2, P0, P1, P2, P3, J) do {                            \
    float4 md = mrow[(J)];                                                     \
    int c = __float_as_int(md.x);                                              \
    uint4 y = *(const uint4*)(YL + (c << 7));                                  \
    VR2 = pk(md.y, md.y);                                                      \
    VI2 = pk(md.z, md.z);                                                      \
    P0 = h2p(y.x); P1 = h2p(y.y); P2 = h2p(y.z); P3 = h2p(y.w);                \
} while (0)

__global__ __launch_bounds__(S_TPB)
void spmm_kernel(const float* __restrict__ Xr, const float* __restrict__ Xi,
                 const uint32_t* __restrict__ Yh, const float4* __restrict__ edge,
                 float* __restrict__ out) {
    __shared__ float4 meta[S_WPB][32];

    int warp = threadIdx.x >> 5;
    int lane = threadIdx.x & 31;
    float4* mrow = meta[warp];
    const uint32_t* YL = Yh + 4 * lane;   // lane owns channels 4l..4l+3 (half2 pairs)
    float* outR = out;
    float* outI = out + NC;

    int gw = blockIdx.x * S_WPB + warp;
    int nw = gridDim.x * S_WPB;

    for (int row = gw; row < N_NODES; row += nw) {
        int e0  = g_off[row];
        int deg = g_off[row + 1] - e0;   // multiple of 4 (pad slots are zero edges)
        u64 acV1[4] = {0ull, 0ull, 0ull, 0ull};
        u64 acV2[4] = {0ull, 0ull, 0ull, 0ull};

        for (int base = 0; base < deg; base += 32) {
            int cnt = min(32, deg - base);   // multiple of 4, >= 4
            if (lane < cnt) mrow[lane] = edge[e0 + base + lane];   // one LDG.128
            __syncwarp();

            u64 vrA, viA, a0, a1, a2, a3;
            u64 vrB, viB, b0, b1, b2, b3;
            u64 vrC, viC, c0, c1, c2, c3;
            u64 vrD, viD, d0, d1, d2, d3;
            SLOT_INIT(vrA, viA, a0, a1, a2, a3, 0);
            SLOT_INIT(vrB, viB, b0, b1, b2, b3, 1);
            SLOT_INIT(vrC, viC, c0, c1, c2, c3, 2);
            SLOT_INIT(vrD, viD, d0, d1, d2, d3, 3);

            for (int j = 0; j < cnt; j += 4) {
                SB(vrA, viA, a0, a1, a2, a3, j);
                SB(vrB, viB, b0, b1, b2, b3, j + 1);
                SB(vrC, viC, c0, c1, c2, c3, j + 2);
                SB(vrD, viD, d0, d1, d2, d3, j + 3);
            }
            __syncwarp();   // protect meta before next chunk restages
        }

        // epilogue: combine pair-accumulators, add residual X, store
        // ar = acV1.lo - acV2.hi ; ai = acV2.lo + acV1.hi
        float r[4], im[4];
        #pragma unroll
        for (int c = 0; c < 4; c++) {
            float s1l, s1h, s2l, s2h;
            upk(acV1[c], s1l, s1h);
            upk(acV2[c], s2l, s2h);
            r[c]  = s1l - s2h;
            im[c] = s2l + s1h;
        }
        float4 rxr = *(const float4*)(Xr + row * CDIM + 4 * lane);
        float4 rxi = *(const float4*)(Xi + row * CDIM + 4 * lane);
        *(float4*)(outR + row * CDIM + 4 * lane) =
            make_float4(r[0] + rxr.x, r[1] + rxr.y, r[2] + rxr.z, r[3] + rxr.w);
        *(float4*)(outI + row * CDIM + 4 * lane) =
            make_float4(im[0] + rxi.x, im[1] + rxi.y, im[2] + rxi.z, im[3] + rxi.w);
    }
}

// ---------------- launch: fork gemm onto a side stream (concurrent graph branches) -------
extern "C" void kernel_launch(void* const* d_in, const int* in_sizes, int n_in,
                              void* d_out, int out_size) {
    const float* Xr = (const float*)d_in[0];
    const float* Xi = (const float*)d_in[1];
    const float* Lr = (const float*)d_in[2];
    const float* Li = (const float*)d_in[3];
    const float* W  = (const float*)d_in[4];
    const int*   row = (const int*)d_in[5];
    const int*   col = (const int*)d_in[6];
    float* out = (float*)d_out;

    // resolve scratch symbol addresses so kernels get true __restrict__ params
    void *yh_p = nullptr, *edge_p = nullptr;
    cudaGetSymbolAddress(&yh_p, g_yh);
    cudaGetSymbolAddress(&edge_p, g_edge);
    uint32_t* Yh = (uint32_t*)yh_p;
    const float4* edge = (const float4*)edge_p;

    cudaFuncSetAttribute(gemm_kernel, cudaFuncAttributeMaxDynamicSharedMemorySize, GM_SMEM);

    cudaStream_t s2 = nullptr;
    cudaEvent_t evFork = nullptr, evGemm = nullptr;
    bool forked =
        (cudaStreamCreateWithFlags(&s2, cudaStreamNonBlocking) == cudaSuccess) &&
        (cudaEventCreateWithFlags(&evFork, cudaEventDisableTiming) == cudaSuccess) &&
        (cudaEventCreateWithFlags(&evGemm, cudaEventDisableTiming) == cudaSuccess);

    if (forked) {
        // fork: side stream inherits capture via event wait
        cudaEventRecord(evFork, 0);
        cudaStreamWaitEvent(s2, evFork, 0);
        gemm_kernel<<<GM_GRID, GM_TPB, GM_SMEM, s2>>>(Xr, Xi, W, Yh);
        cudaEventRecord(evGemm, s2);

        // main chain (edge preprocessing), concurrent with gemm
        hist_kernel<<<(N_EDGES + 255) / 256, 256>>>(row);
        scan_kernel<<<1, 1024>>>();
        scatter_kernel<<<(N_EDGES + 255) / 256, 256>>>(row, col, Lr, Li);

        // join, then spmm consumes both
        cudaStreamWaitEvent(0, evGemm, 0);
        spmm_kernel<<<S_BLOCKS, S_TPB>>>(Xr, Xi, Yh, edge, out);
    } else {
        // fallback: serialized (identical semantics)
        hist_kernel<<<(N_EDGES + 255) / 256, 256>>>(row);
        scan_kernel<<<1, 1024>>>();
        scatter_kernel<<<(N_EDGES + 255) / 256, 256>>>(row, col, Lr, Li);
        gemm_kernel<<<GM_GRID, GM_TPB, GM_SMEM>>>(Xr, Xi, W, Yh);
        spmm_kernel<<<S_BLOCKS, S_TPB>>>(Xr, Xi, Yh, edge, out);
    }
    // note: s2/evFork/evGemm intentionally not destroyed while referenced by the
    // captured graph; kernel_launch runs only a handful of times, so the leak is bounded.
}

// round 17
// speedup vs baseline: 1.6527x; 1.6527x over previous
#include <cuda_runtime.h>
#include <cstdint>

#define N_NODES 50000
#define N_EDGES 800000
#define CDIM 128
#define NC (N_NODES * CDIM)
#define E_CAP (N_EDGES + 4 * N_NODES)   // padded edge capacity

typedef unsigned long long u64;

// ---------------- scratch (static device globals; zero-initialized, no allocation) --------
__device__ int    g_cnt[N_NODES];          // always zero at call entry (scan re-zeroes)
__device__ int    g_off[N_NODES + 1];
__device__ int    g_cur[N_NODES];
__device__ float4 g_edge[E_CAP];           // {col-as-bits, vr, vi, 0}; pad slots stay zero
__device__ u64    g_y[NC * 2 / 2];         // (yr,yi) pairs? -- see layout below
__device__ u64    g_ypad[2];               // guard (unused)

// NOTE: g_y layout = [row][channel] interleaved (yr, yi) u64 pairs? NO --
// this build uses the R12 layout: two separate fp32 planes addressed via one base.
__device__ float  g_yr[NC];                // Y_real = X_real @ W
__device__ float  g_yi[NC];                // Y_imag = X_imag @ W

// ---------------- packed f32x2 helpers ----------------
__device__ __forceinline__ u64 pk(float lo, float hi) {
    u64 r; asm("mov.b64 %0, {%1,%2};" : "=l"(r) : "f"(lo), "f"(hi)); return r;
}
__device__ __forceinline__ void upk(u64 v, float& lo, float& hi) {
    asm("mov.b64 {%0,%1}, %2;" : "=f"(lo), "=f"(hi) : "l"(v));
}
__device__ __forceinline__ u64 ffma2(u64 a, u64 b, u64 c) {
    u64 d; asm("fma.rn.f32x2 %0, %1, %2, %3;" : "=l"(d) : "l"(a), "l"(b), "l"(c)); return d;
}

// ---------------- counting sort pipeline (pad-to-4 offsets) ----------------
__global__ void hist_kernel(const int* __restrict__ row) {
    int e = blockIdx.x * blockDim.x + threadIdx.x;
    if (e < N_EDGES) atomicAdd(&g_cnt[row[e]], 1);
}

// single-block coalesced scan: 1024 threads, 49 chunk iterations, shfl block-scan
__global__ __launch_bounds__(1024)
void scan_kernel() {
    __shared__ int wsum[32];
    int t = threadIdx.x, lane = t & 31, wid = t >> 5;
    int run = 0;
    const int ITERS = (N_NODES + 1023) / 1024;  // 49
    for (int it = 0; it < ITERS; it++) {
        int idx = it * 1024 + t;
        int c = (idx < N_NODES) ? g_cnt[idx] : 0;
        int v = (c + 3) & ~3;
        int s = v;
        #pragma unroll
        for (int d = 1; d < 32; d <<= 1) {
            int u = __shfl_up_sync(0xffffffffu, s, d);
            if (lane >= d) s += u;
        }
        if (lane == 31) wsum[wid] = s;
        __syncthreads();
        if (wid == 0) {
            int ws = wsum[lane];
            #pragma unroll
            for (int d = 1; d < 32; d <<= 1) {
                int u = __shfl_up_sync(0xffffffffu, ws, d);
                if (lane >= d) ws += u;
            }
            wsum[lane] = ws;
        }
        __syncthreads();
        int base = (wid > 0) ? wsum[wid - 1] : 0;
        int excl = run + base + s - v;
        if (idx < N_NODES) {
            g_off[idx] = excl;
            g_cur[idx] = excl;
            g_cnt[idx] = 0;          // restore invariant for next call
        }
        run += wsum[31];
        __syncthreads();             // protect wsum before next iteration
    }
    if (t == 0) g_off[N_NODES] = run;
}

__global__ void scatter_kernel(const int* __restrict__ row, const int* __restrict__ col,
                               const float* __restrict__ lr, const float* __restrict__ li) {
    int e = blockIdx.x * blockDim.x + threadIdx.x;
    if (e < N_EDGES) {
        int r = row[e];
        int p = atomicAdd(&g_cur[r], 1);
        g_edge[p] = make_float4(__int_as_float(col[e]), lr[e], li[e], 0.0f);
    }
}

// ---------------- GEMM kernel: (Yr,Yi) = (Xr,Xi) @ W, complex-pair packed ----------------
// W staged ONCE per block (64KB); A-tile prefetched into registers one tile ahead so no
// global-load latency is exposed at barriers. 2 barriers/tile. 96KB smem -> 2 blocks/SM.
#define GM_TPB    256
#define GM_WPB    8
#define GM_RPW    4
#define GM_ROWS   (GM_WPB * GM_RPW)                      // 32 rows / tile
#define GM_TILES  ((N_NODES + GM_ROWS - 1) / GM_ROWS)    // 1563
#define GM_GRID   (148 * 2)                              // 296 = one full wave @ 2 blk/SM
#define GM_SMEM   (CDIM * CDIM * 4 + GM_ROWS * CDIM * 8) // 64KB W + 32KB A = 98304

#define LOAD_A_REGS(TILE) do {                                                  \
    int rb_ = (TILE) * GM_ROWS + warp * GM_RPW;                                 \
    _Pragma("unroll")                                                           \
    for (int rr = 0; rr < GM_RPW; rr++) {                                       \
        int row_ = min(rb_ + rr, N_NODES - 1);                                  \
        pr[rr][0] = *(const float2*)(Xr + row_ * CDIM + 2 * lane);              \
        pi[rr][0] = *(const float2*)(Xi + row_ * CDIM + 2 * lane);              \
        pr[rr][1] = *(const float2*)(Xr + row_ * CDIM + 64 + 2 * lane);         \
        pi[rr][1] = *(const float2*)(Xi + row_ * CDIM + 64 + 2 * lane);         \
    }                                                                           \
} while (0)

__global__ __launch_bounds__(GM_TPB, 2)
void gemm_kernel(const float* __restrict__ Xr, const float* __restrict__ Xi,
                 const float* __restrict__ W,
                 float* __restrict__ Yr, float* __restrict__ Yi) {
    extern __shared__ char smraw[];
    float* Wt = (float*)smraw;                        // [128][128], staged once
    u64*   At = (u64*)(smraw + CDIM * CDIM * 4);      // [32 rows][128] (xr,xi) pairs

    int tid  = threadIdx.x;
    int warp = tid >> 5;
    int lane = tid & 31;

    // stage full W once (coalesced float4; 16 per thread)
    {
        const float4* s4 = (const float4*)W;
        float4* d4 = (float4*)Wt;
        #pragma unroll
        for (int i = 0; i < CDIM * CDIM / 4 / GM_TPB; i++)
            d4[i * GM_TPB + tid] = s4[i * GM_TPB + tid];
    }

    // prologue: prefetch first tile's A into registers
    float2 pr[GM_RPW][2], pi[GM_RPW][2];
    LOAD_A_REGS(blockIdx.x);
    __syncthreads();   // W ready

    for (int tile = blockIdx.x; tile < GM_TILES; tile += GM_GRID) {
        int rbase = tile * GM_ROWS + warp * GM_RPW;

        // STS prefetched A (register-sourced, no global latency at this barrier)
        #pragma unroll
        for (int rr = 0; rr < GM_RPW; rr++) {
            #pragma unroll
            for (int seg = 0; seg < 2; seg++) {
                ulonglong2 v;
                v.x = pk(pr[rr][seg].x, pi[rr][seg].x);
                v.y = pk(pr[rr][seg].y, pi[rr][seg].y);
                *(ulonglong2*)&At[(warp * GM_RPW + rr) * CDIM + seg * 64 + 2 * lane] = v;
            }
        }
        __syncthreads();

        // prefetch NEXT tile's A now; latency hides under this tile's compute
        int nt = tile + GM_GRID;
        if (nt < GM_TILES) LOAD_A_REGS(nt);

        u64 acc[GM_RPW][4];
        #pragma unroll
        for (int rr = 0; rr < GM_RPW; rr++)
            #pragma unroll
            for (int c = 0; c < 4; c++) acc[rr][c] = 0ull;

        const u64* Aw = At + warp * GM_RPW * CDIM;
        #pragma unroll 8
        for (int kk = 0; kk < CDIM; kk += 2) {
            float4 w4a = *(const float4*)&Wt[kk * CDIM + 4 * lane];
            float4 w4b = *(const float4*)&Wt[(kk + 1) * CDIM + 4 * lane];
            u64 wa0 = pk(w4a.x, w4a.x), wa1 = pk(w4a.y, w4a.y);
            u64 wa2 = pk(w4a.z, w4a.z), wa3 = pk(w4a.w, w4a.w);
            u64 wb0 = pk(w4b.x, w4b.x), wb1 = pk(w4b.y, w4b.y);
            u64 wb2 = pk(w4b.z, w4b.z), wb3 = pk(w4b.w, w4b.w);
            #pragma unroll
            for (int rr = 0; rr < GM_RPW; rr++) {
                ulonglong2 a = *(const ulonglong2*)&Aw[rr * CDIM + kk];
                acc[rr][0] = ffma2(a.x, wa0, acc[rr][0]);
                acc[rr][1] = ffma2(a.x, wa1, acc[rr][1]);
                acc[rr][2] = ffma2(a.x, wa2, acc[rr][2]);
                acc[rr][3] = ffma2(a.x, wa3, acc[rr][3]);
                acc[rr][0] = ffma2(a.y, wb0, acc[rr][0]);
                acc[rr][1] = ffma2(a.y, wb1, acc[rr][1]);
                acc[rr][2] = ffma2(a.y, wb2, acc[rr][2]);
                acc[rr][3] = ffma2(a.y, wb3, acc[rr][3]);
            }
        }

        // write Y, then release At for the next tile's STS
        #pragma unroll
        for (int rr = 0; rr < GM_RPW; rr++) {
            int row = rbase + rr;
            if (row < N_NODES) {
                float4 r4, i4;
                upk(acc[rr][0], r4.x, i4.x);
                upk(acc[rr][1], r4.y, i4.y);
                upk(acc[rr][2], r4.z, i4.z);
                upk(acc[rr][3], r4.w, i4.w);
                *(float4*)(Yr + row * CDIM + 4 * lane) = r4;
                *(float4*)(Yi + row * CDIM + 4 * lane) = i4;
            }
        }
        __syncthreads();
    }
}

// ---------------- SpMM kernel: out = L_complex @ Y + X (gather + residual) --------------
#define S_TPB 256
#define S_WPB 8
#define S_BLOCKS (148 * 3)   // 444 = one full wave at 3 blocks/SM

#define SB(MD, YR, YI, J) do {                                                 \
    u64 vr2 = pk(MD.y, MD.y), vi2 = pk(MD.z, MD.z), nvi2 = pk(-MD.z, -MD.z);   \
    ar01 = ffma2(vr2,  YR.x, ar01); ar23 = ffma2(vr2,  YR.y, ar23);            \
    ai01 = ffma2(vi2,  YR.x, ai01); ai23 = ffma2(vi2,  YR.y, ai23);            \
    ar01 = ffma2(nvi2, YI.x, ar01); ar23 = ffma2(nvi2, YI.y, ar23);            \
    ai01 = ffma2(vr2,  YI.x, ai01); ai23 = ffma2(vr2,  YI.y, ai23);            \
    int jn = (J) + 4;                                                          \
    if (jn < cnt) {                                                            \
        MD = mrow[jn];                                                         \
        int c = __float_as_int(MD.x);                                          \
        YR = *(const ulonglong2*)(YrL + (c << 7));                             \
        YI = *(const ulonglong2*)(YiL + (c << 7));                             \
    }                                                                          \
} while (0)

__global__ __launch_bounds__(S_TPB)
void spmm_kernel(const float* __restrict__ Xr, const float* __restrict__ Xi,
                 const float* __restrict__ Yr, const float* __restrict__ Yi,
                 const float4* __restrict__ edge, float* __restrict__ out) {
    __shared__ float4 meta[S_WPB][32];

    int warp = threadIdx.x >> 5;
    int lane = threadIdx.x & 31;
    float4* mrow = meta[warp];
    const float* YrL = Yr + 4 * lane;
    const float* YiL = Yi + 4 * lane;
    float* outR = out;
    float* outI = out + NC;

    int gw = blockIdx.x * S_WPB + warp;
    int nw = gridDim.x * S_WPB;

    for (int row = gw; row < N_NODES; row += nw) {
        int e0  = g_off[row];
        int deg = g_off[row + 1] - e0;   // multiple of 4 (pad slots are zero edges)
        u64 ar01 = 0, ar23 = 0, ai01 = 0, ai23 = 0;

        for (int base = 0; base < deg; base += 32) {
            int cnt = min(32, deg - base);   // multiple of 4, >= 4
            if (lane < cnt) mrow[lane] = edge[e0 + base + lane];   // one LDG.128
            __syncwarp();

            float4 md0 = mrow[0], md1 = mrow[1], md2 = mrow[2], md3 = mrow[3];
            ulonglong2 yr0, yi0, yr1, yi1, yr2, yi2, yr3, yi3;
            {
                int c0 = __float_as_int(md0.x), c1 = __float_as_int(md1.x);
                int c2 = __float_as_int(md2.x), c3 = __float_as_int(md3.x);
                yr0 = *(const ulonglong2*)(YrL + (c0 << 7));
                yi0 = *(const ulonglong2*)(YiL + (c0 << 7));
                yr1 = *(const ulonglong2*)(YrL + (c1 << 7));
                yi1 = *(const ulonglong2*)(YiL + (c1 << 7));
                yr2 = *(const ulonglong2*)(YrL + (c2 << 7));
                yi2 = *(const ulonglong2*)(YiL + (c2 << 7));
                yr3 = *(const ulonglong2*)(YrL + (c3 << 7));
                yi3 = *(const ulonglong2*)(YiL + (c3 << 7));
            }
            for (int j = 0; j < cnt; j += 4) {
                SB(md0, yr0, yi0, j);
                SB(md1, yr1, yi1, j + 1);
                SB(md2, yr2, yi2, j + 2);
                SB(md3, yr3, yi3, j + 3);
            }
            __syncwarp();   // protect meta before next chunk restages
        }

        // epilogue: unpack, add residual X, store
        float a0, a1, a2, a3, b0, b1, b2, b3;
        upk(ar01, a0, a1); upk(ar23, a2, a3);
        upk(ai01, b0, b1); upk(ai23, b2, b3);
        float4 rxr = *(const float4*)(Xr + row * CDIM + 4 * lane);
        float4 rxi = *(const float4*)(Xi + row * CDIM + 4 * lane);
        *(float4*)(outR + row * CDIM + 4 * lane) =
            make_float4(a0 + rxr.x, a1 + rxr.y, a2 + rxr.z, a3 + rxr.w);
        *(float4*)(outI + row * CDIM + 4 * lane) =
            make_float4(b0 + rxi.x, b1 + rxi.y, b2 + rxi.z, b3 + rxi.w);
    }
}

// ---------------- launch: same concurrent graph as R12, but gemm submitted 4th so the
// profiler (4th-submission slot) finally captures it in the forked context. -------------
extern "C" void kernel_launch(void* const* d_in, const int* in_sizes, int n_in,
                              void* d_out, int out_size) {
    const float* Xr = (const float*)d_in[0];
    const float* Xi = (const float*)d_in[1];
    const float* Lr = (const float*)d_in[2];
    const float* Li = (const float*)d_in[3];
    const float* W  = (const float*)d_in[4];
    const int*   row = (const int*)d_in[5];
    const int*   col = (const int*)d_in[6];
    float* out = (float*)d_out;

    // resolve scratch symbol addresses so kernels get true __restrict__ params
    void *yr_p = nullptr, *yi_p = nullptr, *edge_p = nullptr;
    cudaGetSymbolAddress(&yr_p, g_yr);
    cudaGetSymbolAddress(&yi_p, g_yi);
    cudaGetSymbolAddress(&edge_p, g_edge);
    float* Yr = (float*)yr_p;
    float* Yi = (float*)yi_p;
    const float4* edge = (const float4*)edge_p;

    cudaFuncSetAttribute(gemm_kernel, cudaFuncAttributeMaxDynamicSharedMemorySize, GM_SMEM);

    cudaStream_t s2 = nullptr;
    cudaEvent_t evFork = nullptr, evGemm = nullptr;
    bool forked =
        (cudaStreamCreateWithFlags(&s2, cudaStreamNonBlocking) == cudaSuccess) &&
        (cudaEventCreateWithFlags(&evFork, cudaEventDisableTiming) == cudaSuccess) &&
        (cudaEventCreateWithFlags(&evGemm, cudaEventDisableTiming) == cudaSuccess);

    if (forked) {
        // fork point recorded BEFORE prep so gemm's graph deps are just the fork
        cudaEventRecord(evFork, 0);
        cudaStreamWaitEvent(s2, evFork, 0);

        // main chain first (submissions 1-3): edge preprocessing
        hist_kernel<<<(N_EDGES + 255) / 256, 256>>>(row);
        scan_kernel<<<1, 1024>>>();
        scatter_kernel<<<(N_EDGES + 255) / 256, 256>>>(row, col, Lr, Li);

        // gemm submitted 4th, but depends only on evFork -> runs CONCURRENT with prep
        gemm_kernel<<<GM_GRID, GM_TPB, GM_SMEM, s2>>>(Xr, Xi, W, Yr, Yi);
        cudaEventRecord(evGemm, s2);

        // join, then spmm consumes both
        cudaStreamWaitEvent(0, evGemm, 0);
        spmm_kernel<<<S_BLOCKS, S_TPB>>>(Xr, Xi, Yr, Yi, edge, out);
    } else {
        // fallback: serialized (identical semantics)
        hist_kernel<<<(N_EDGES + 255) / 256, 256>>>(row);
        scan_kernel<<<1, 1024>>>();
        scatter_kernel<<<(N_EDGES + 255) / 256, 256>>>(row, col, Lr, Li);
        gemm_kernel<<<GM_GRID, GM_TPB, GM_SMEM>>>(Xr, Xi, W, Yr, Yi);
        spmm_kernel<<<S_BLOCKS, S_TPB>>>(Xr, Xi, Yr, Yi, edge, out);
    }
    // note: s2/evFork/evGemm intentionally not destroyed while referenced by the
    // captured graph; kernel_launch runs only a handful of times, so the leak is bounded.
}